// round 1
// baseline (speedup 1.0000x reference)
#include <cuda_runtime.h>
#include <cuda_bf16.h>

#define HW      589824      // 768*768
#define NG      147456      // HW/4
#define BPB     74          // blocks per batch
#define TPB     128
#define NB      8
#define NC      9           // classes / channels
#define NPACK   5           // 10 values (9 channels + count) as float2

// scratch: per (batch, block, class) partials: 9 channel-sums + count
__device__ float g_scratch[NB * BPB * NC * 10];

__global__ void __launch_bounds__(TPB, 4) accum_kernel(
    const int* __restrict__ masks, const float* __restrict__ outs)
{
    // per-lane-private accumulators: [warp][class][pack][lane], lane innermost
    __shared__ float2 sh[4 * NC * NPACK * 32];   // 46080 bytes

    const int tid  = threadIdx.x;
    const int lane = tid & 31;
    const int w    = tid >> 5;
    const int b    = blockIdx.y;
    const int blk  = blockIdx.x;

    // zero shared accumulators
    float* shf = (float*)sh;
    #pragma unroll
    for (int i = tid; i < 4 * NC * NPACK * 32 * 2; i += TPB) shf[i] = 0.0f;
    __syncthreads();

    const int4*   m4     = (const int4*)(masks + (size_t)b * HW);
    const float4* o4base = (const float4*)(outs + (size_t)b * NC * HW);

    for (int g = blk * TPB + tid; g < NG; g += BPB * TPB) {
        int4 mm = m4[g];
        float4 v[NC];
        #pragma unroll
        for (int c = 0; c < NC; c++) v[c] = o4base[(size_t)c * NG + g];

        #pragma unroll
        for (int j = 0; j < 4; j++) {
            int m = (j == 0) ? mm.x : (j == 1) ? mm.y : (j == 2) ? mm.z : mm.w;
            m = min(max(m, 0), NC - 1);
            float2* base = sh + ((w * NC + m) * NPACK) * 32 + lane;

            float pv[10];
            #pragma unroll
            for (int c = 0; c < NC; c++)
                pv[c] = (j == 0) ? v[c].x : (j == 1) ? v[c].y : (j == 2) ? v[c].z : v[c].w;
            pv[9] = 1.0f;   // count channel

            #pragma unroll
            for (int p = 0; p < NPACK; p++) {
                float2 a = base[p * 32];
                a.x += pv[2 * p];
                a.y += pv[2 * p + 1];
                base[p * 32] = a;
            }
        }
    }
    __syncthreads();

    // block reduction over (warp, lane) -> 9 classes x 10 values
    if (tid < NC * 10) {
        int m  = tid / 10;
        int cc = tid % 10;
        int p  = cc >> 1;
        int hf = cc & 1;
        float s = 0.0f;
        #pragma unroll
        for (int wi = 0; wi < 4; wi++) {
            #pragma unroll 8
            for (int l = 0; l < 32; l++) {
                float2 a = sh[((wi * NC + m) * NPACK + p) * 32 + l];
                s += hf ? a.y : a.x;
            }
        }
        g_scratch[((b * BPB + blk) * NC + m) * 10 + cc] = s;
    }
}

__global__ void finalize_kernel(float* __restrict__ out)
{
    __shared__ float tot[NB][NC][10];
    __shared__ float per[64];
    __shared__ float pres[64];
    const int tid = threadIdx.x;

    if (tid < NB * NC * 10) {
        int b  = tid / (NC * 10);
        int r  = tid % (NC * 10);
        int m  = r / 10;
        int cc = r % 10;
        float s = 0.0f;
        #pragma unroll 2
        for (int blk = 0; blk < BPB; blk++)
            s += g_scratch[((b * BPB + blk) * NC + m) * 10 + cc];
        tot[b][m][cc] = s;
    }
    __syncthreads();

    if (tid < 64) {
        int b = tid / 8;
        int k = tid % 8 + 1;            // classes 1..8
        float cnt   = tot[b][k][9];
        float denom = fmaxf(cnt, 1.0f);
        float p[NC];
        float mx = -1e30f;
        #pragma unroll
        for (int c = 0; c < NC; c++) {
            p[c] = tot[b][k][c] / denom;
            mx = fmaxf(mx, p[c]);
        }
        float se = 0.0f;
        #pragma unroll
        for (int c = 0; c < NC; c++) se += expf(p[c] - mx);
        float lse = mx + logf(se);
        float l = 0.0f;
        #pragma unroll
        for (int c = 0; c < NC; c++) {
            float tgt = (c == k) ? 0.9f : 0.0125f;
            l += tgt * (p[c] - lse);
        }
        bool present = cnt > 0.0f;
        per[tid]  = present ? -l   : 0.0f;
        pres[tid] = present ? 1.0f : 0.0f;
    }
    __syncthreads();

    if (tid == 0) {
        float L = 0.0f, P = 0.0f;
        #pragma unroll
        for (int i = 0; i < 64; i++) { L += per[i]; P += pres[i]; }
        out[0] = L / fmaxf(P, 1.0f);
    }
}

extern "C" void kernel_launch(void* const* d_in, const int* in_sizes, int n_in,
                              void* d_out, int out_size)
{
    // identify inputs by element count (masks = B*H*W, outputs = B*9*H*W)
    const int* masks;
    const float* outs;
    if (in_sizes[0] == NB * HW) {
        masks = (const int*)d_in[0];
        outs  = (const float*)d_in[1];
    } else {
        masks = (const int*)d_in[1];
        outs  = (const float*)d_in[0];
    }
    float* out = (float*)d_out;

    static bool configured = false;
    if (!configured) {
        // bias carveout toward shared so 4 blocks x 46080B fit per SM
        cudaFuncSetAttribute(accum_kernel,
                             cudaFuncAttributePreferredSharedMemoryCarveout, 100);
        configured = true;
    }

    dim3 grid(BPB, NB);
    accum_kernel<<<grid, TPB>>>(masks, outs);
    finalize_kernel<<<1, 768>>>(out);
}

// round 2
// speedup vs baseline: 1.0963x; 1.0963x over previous
#include <cuda_runtime.h>
#include <cuda_bf16.h>

#define HW      589824      // 768*768
#define NG      147456      // HW/4
#define BPB     74          // blocks per batch
#define TPB     128
#define NB      8
#define NC      9           // classes / channels
#define NPACK   5           // 10 values (9 channels + count) as float2
#define NOUT    90          // 9 classes * 10 values

// stage-1 partials: [batch][block][90], stage-2 totals: [batch][90]
__device__ float g_part[NB * BPB * NOUT];
__device__ float g_tot[NB * NOUT];
__device__ int   g_bcnt[NB];   // zero-initialized; reset by final block each call
__device__ int   g_fcnt;

__global__ void __launch_bounds__(TPB, 4) fused_kernel(
    const int* __restrict__ masks, const float* __restrict__ outs,
    float* __restrict__ out)
{
    // per-lane-private accumulators: [warp][class][pack][lane], lane innermost
    __shared__ float2 sh[4 * NC * NPACK * 32];   // 46080 bytes
    __shared__ int s_last;
    __shared__ float per[64], pres[64];

    const int tid  = threadIdx.x;
    const int lane = tid & 31;
    const int w    = tid >> 5;
    const int b    = blockIdx.y;
    const int blk  = blockIdx.x;

    // zero shared accumulators
    float* shf = (float*)sh;
    #pragma unroll
    for (int i = tid; i < 4 * NC * NPACK * 64; i += TPB) shf[i] = 0.0f;
    __syncthreads();

    const int4*   m4 = (const int4*)(masks + (size_t)b * HW);
    const float4* o4 = (const float4*)(outs + (size_t)b * NC * HW);

    for (int g = blk * TPB + tid; g < NG; g += BPB * TPB) {
        int4 mm = m4[g];
        float4 v[NC];
        #pragma unroll
        for (int c = 0; c < NC; c++) v[c] = o4[(size_t)c * NG + g];

        #pragma unroll
        for (int j = 0; j < 4; j++) {
            int m = (j == 0) ? mm.x : (j == 1) ? mm.y : (j == 2) ? mm.z : mm.w;
            m = min(max(m, 0), NC - 1);
            float2* base = sh + ((w * NC + m) * NPACK) * 32 + lane;

            float pv[10];
            #pragma unroll
            for (int c = 0; c < NC; c++)
                pv[c] = (j == 0) ? v[c].x : (j == 1) ? v[c].y : (j == 2) ? v[c].z : v[c].w;
            pv[9] = 1.0f;   // count channel

            #pragma unroll
            for (int p = 0; p < NPACK; p++) {
                float2 a = base[p * 32];
                a.x += pv[2 * p];
                a.y += pv[2 * p + 1];
                base[p * 32] = a;
            }
        }
    }
    __syncthreads();

    // fold warp regions 1..3 into warp 0's region (all 128 threads)
    for (int i = tid; i < NC * NPACK * 32; i += TPB) {
        float2 a = sh[i];
        float2 x = sh[i + 1440], y = sh[i + 2880], z = sh[i + 4320];
        a.x += x.x + y.x + z.x;
        a.y += x.y + y.y + z.y;
        sh[i] = a;
    }
    __syncthreads();

    // 32-lane sums -> 90 partials for this block
    if (tid < NOUT) {
        int m = tid / 10, cc = tid % 10, p = cc >> 1, hf = cc & 1;
        float s = 0.0f;
        #pragma unroll 8
        for (int l = 0; l < 32; l++) {
            float2 a = sh[(m * NPACK + p) * 32 + l];
            s += hf ? a.y : a.x;
        }
        g_part[(b * BPB + blk) * NOUT + tid] = s;
    }
    __threadfence();
    __syncthreads();
    if (tid == 0) s_last = (atomicAdd(&g_bcnt[b], 1) == BPB - 1);
    __syncthreads();
    if (!s_last) return;

    // ── per-batch reducer (runs in 8 blocks, one per batch, in parallel) ──
    __threadfence();
    if (tid < NOUT) {
        float s = 0.0f;
        #pragma unroll 2
        for (int k = 0; k < BPB; k++)
            s += g_part[(b * BPB + k) * NOUT + tid];
        g_tot[b * NOUT + tid] = s;
    }
    __threadfence();
    __syncthreads();
    if (tid == 0) s_last = (atomicAdd(&g_fcnt, 1) == NB - 1);
    __syncthreads();
    if (!s_last) return;

    // ── global final block: log-softmax loss over 64 protos ──
    __threadfence();
    if (tid < 64) {
        int bb = tid / 8, k = tid % 8 + 1;   // classes 1..8
        float cnt   = g_tot[bb * NOUT + k * 10 + 9];
        float denom = fmaxf(cnt, 1.0f);
        float p[NC], mx = -1e30f;
        #pragma unroll
        for (int c = 0; c < NC; c++) {
            p[c] = g_tot[bb * NOUT + k * 10 + c] / denom;
            mx = fmaxf(mx, p[c]);
        }
        float se = 0.0f;
        #pragma unroll
        for (int c = 0; c < NC; c++) se += expf(p[c] - mx);
        float lse = mx + logf(se);
        float l = 0.0f;
        #pragma unroll
        for (int c = 0; c < NC; c++) {
            float tgt = (c == k) ? 0.9f : 0.0125f;
            l += tgt * (p[c] - lse);
        }
        bool present = cnt > 0.0f;
        per[tid]  = present ? -l   : 0.0f;
        pres[tid] = present ? 1.0f : 0.0f;
    }
    __syncthreads();
    if (tid == 0) {
        float L = 0.0f, P = 0.0f;
        #pragma unroll
        for (int i = 0; i < 64; i++) { L += per[i]; P += pres[i]; }
        out[0] = L / fmaxf(P, 1.0f);
        g_fcnt = 0;                      // reset for next graph replay
    }
    if (tid < NB) g_bcnt[tid] = 0;       // reset batch counters
}

extern "C" void kernel_launch(void* const* d_in, const int* in_sizes, int n_in,
                              void* d_out, int out_size)
{
    const int* masks;
    const float* outs;
    if (in_sizes[0] == NB * HW) {
        masks = (const int*)d_in[0];
        outs  = (const float*)d_in[1];
    } else {
        masks = (const int*)d_in[1];
        outs  = (const float*)d_in[0];
    }
    float* out = (float*)d_out;

    static bool configured = false;
    if (!configured) {
        cudaFuncSetAttribute(fused_kernel,
                             cudaFuncAttributePreferredSharedMemoryCarveout, 100);
        configured = true;
    }

    dim3 grid(BPB, NB);
    fused_kernel<<<grid, TPB>>>(masks, outs, out);
}